// round 2
// baseline (speedup 1.0000x reference)
#include <cuda_runtime.h>
#include <math.h>

#define NN      4096
#define IN_DIM  128
#define HEADS   4
#define OUT_DIM 64
#define HD      256   // HEADS*OUT_DIM
#define NEG_INF (-9.0e15f)

#define BM 32
#define BN 64
#define MPAD 72       // padded mask row stride (bytes)

// persistent scratch (allocation-free rule: __device__ globals)
__device__ float g_h[NN * HD];      // 4 MB
__device__ float g_si[NN * HEADS];
__device__ float g_sj[NN * HEADS];

// --------------------------------------------------------------------------
// Kernel 1: h = x @ W    (4096x128) @ (128x256)
// --------------------------------------------------------------------------
__global__ __launch_bounds__(256) void gemm_h_kernel(const float* __restrict__ x,
                                                     const float* __restrict__ W) {
    __shared__ float xs[32][IN_DIM];
    const int t = threadIdx.x;
    const int row0 = blockIdx.x * 32;

    for (int idx = t; idx < 32 * IN_DIM; idx += 256)
        xs[idx / IN_DIM][idx % IN_DIM] = x[row0 * IN_DIM + idx];
    __syncthreads();

    const int slot = t & 63;
    const int grp  = t >> 6;
    float4 acc[8];
#pragma unroll
    for (int r = 0; r < 8; r++) acc[r] = make_float4(0.f, 0.f, 0.f, 0.f);

    const float4* W4 = (const float4*)W;
#pragma unroll 4
    for (int k = 0; k < IN_DIM; k++) {
        float4 wv = W4[k * 64 + slot];
#pragma unroll
        for (int r = 0; r < 8; r++) {
            float xv = xs[grp * 8 + r][k];
            acc[r].x = fmaf(xv, wv.x, acc[r].x);
            acc[r].y = fmaf(xv, wv.y, acc[r].y);
            acc[r].z = fmaf(xv, wv.z, acc[r].z);
            acc[r].w = fmaf(xv, wv.w, acc[r].w);
        }
    }
    float4* H4 = (float4*)g_h;
#pragma unroll
    for (int r = 0; r < 8; r++)
        H4[(size_t)(row0 + grp * 8 + r) * 64 + slot] = acc[r];
}

// --------------------------------------------------------------------------
// Kernel 2: s_i = h . a_src,  s_j = h . a_dst  per (node, head)
// --------------------------------------------------------------------------
__global__ __launch_bounds__(256) void score_vec_kernel(const float* __restrict__ a_src,
                                                        const float* __restrict__ a_dst) {
    int t = blockIdx.x * 256 + threadIdx.x;
    if (t >= NN * HEADS) return;
    int n = t >> 2, h = t & 3;
    const float4* hv  = (const float4*)(g_h + (size_t)n * HD + h * OUT_DIM);
    const float4* as4 = (const float4*)a_src;
    const float4* ad4 = (const float4*)a_dst;
    float si = 0.f, sj = 0.f;
#pragma unroll
    for (int q = 0; q < 16; q++) {
        float4 v = hv[q], a = as4[q], b = ad4[q];
        si += v.x * a.x + v.y * a.y + v.z * a.z + v.w * a.w;
        sj += v.x * b.x + v.y * b.y + v.z * b.z + v.w * b.w;
    }
    g_si[t] = si;
    g_sj[t] = sj;
}

// --------------------------------------------------------------------------
// Kernel 3: fused masked-softmax attention + aggregation (flash style)
// --------------------------------------------------------------------------
#define SM_H      0
#define SM_P      65536
#define SM_SJ     (65536 + 32768)
#define SM_SI     (SM_SJ + 1024)
#define SM_SCALE  (SM_SI + 512)
#define SM_L      (SM_SCALE + 512)
#define SM_MASK   (SM_L + 512)
#define SM_TOTAL  (SM_MASK + BM * MPAD)

__global__ __launch_bounds__(256) void gat_attn_kernel(const int* __restrict__ mask,
                                                       float* __restrict__ out) {
    extern __shared__ __align__(16) char smem[];
    float4*        h_sh     = (float4*)(smem + SM_H);
    float*         p_sh     = (float*)(smem + SM_P);
    float*         sj_sh    = (float*)(smem + SM_SJ);
    float*         si_sh    = (float*)(smem + SM_SI);
    float*         scale_sh = (float*)(smem + SM_SCALE);
    float*         l_sh     = (float*)(smem + SM_L);
    unsigned char* mask_sh  = (unsigned char*)(smem + SM_MASK);

    const int t  = threadIdx.x;
    const int i0 = blockIdx.x * BM;

    if (t < BM * HEADS) si_sh[t] = g_si[i0 * HEADS + t];   // [i][h]

    const int slot = t & 63;          // 4-dim slot (covers all 256 dims)
    const int grp  = t >> 6;          // 8-row group
    const int hb   = slot >> 4;       // head for pass B
    float4 acc[8];
#pragma unroll
    for (int r = 0; r < 8; r++) acc[r] = make_float4(0.f, 0.f, 0.f, 0.f);

    // pass-A identity (threads 0..127): one (i, head) pair each
    const int ia = t & 31;
    const int ha = t >> 5;
    float m_run = -INFINITY, l_run = 0.0f, si_a = 0.0f;
    __syncthreads();
    if (t < 128) si_a = si_sh[ia * HEADS + ha];

    const float4* gh4 = (const float4*)g_h;
    const int4* mask4 = (const int4*)mask;

    for (int j0 = 0; j0 < NN; j0 += BN) {
        // ---- stage tile ----
#pragma unroll
        for (int it = 0; it < 16; it++) {
            int idx = t + it * 256;
            h_sh[idx] = gh4[(size_t)j0 * 64 + idx];
        }
        sj_sh[t] = g_sj[j0 * HEADS + t];                    // [j][h]
        // mask is int32 (bool normalized by harness). BM rows x 16 int4 words.
#pragma unroll
        for (int idx = t; idx < BM * 16; idx += 256) {
            int row = idx >> 4, w = idx & 15;
            int4 mv = mask4[(size_t)(i0 + row) * (NN / 4) + (j0 >> 2) + w];
            unsigned char* mdst = mask_sh + row * MPAD + w * 4;
            mdst[0] = (unsigned char)(mv.x != 0);
            mdst[1] = (unsigned char)(mv.y != 0);
            mdst[2] = (unsigned char)(mv.z != 0);
            mdst[3] = (unsigned char)(mv.w != 0);
        }
        __syncthreads();

        // ---- pass A: scores + online softmax bookkeeping ----
        if (t < 128) {
            float tmax = -INFINITY;
            float* prow = p_sh + ha * (BN * BM) + ia;       // p_sh[ha][j][ia]
#pragma unroll 4
            for (int j = 0; j < BN; j++) {
                float s = si_a + sj_sh[j * HEADS + ha];
                s = fmaxf(s, 0.2f * s);                     // leaky_relu(0.2)
                if (!mask_sh[ia * MPAD + j]) s = NEG_INF;
                prow[j * BM] = s;
                tmax = fmaxf(tmax, s);
            }
            float m_new = fmaxf(m_run, tmax);
            float scale = __expf(m_run - m_new);
            scale_sh[ha * BM + ia] = scale;
            float sum = 0.0f;
#pragma unroll 4
            for (int j = 0; j < BN; j++) {
                float p = __expf(prow[j * BM] - m_new);
                prow[j * BM] = p;
                sum += p;
            }
            l_run = l_run * scale + sum;
            m_run = m_new;
        }
        __syncthreads();

        // ---- pass B: rescale + accumulate P @ H ----
#pragma unroll
        for (int r = 0; r < 8; r++) {
            float sc = scale_sh[hb * BM + grp * 8 + r];
            acc[r].x *= sc; acc[r].y *= sc; acc[r].z *= sc; acc[r].w *= sc;
        }
        const float4* p4 = (const float4*)p_sh;
#pragma unroll 4
        for (int j = 0; j < BN; j++) {
            float4 hv = h_sh[j * 64 + slot];
            float4 pa = p4[(hb * BN + j) * 8 + grp * 2];
            float4 pb = p4[(hb * BN + j) * 8 + grp * 2 + 1];
            acc[0].x = fmaf(pa.x, hv.x, acc[0].x); acc[0].y = fmaf(pa.x, hv.y, acc[0].y);
            acc[0].z = fmaf(pa.x, hv.z, acc[0].z); acc[0].w = fmaf(pa.x, hv.w, acc[0].w);
            acc[1].x = fmaf(pa.y, hv.x, acc[1].x); acc[1].y = fmaf(pa.y, hv.y, acc[1].y);
            acc[1].z = fmaf(pa.y, hv.z, acc[1].z); acc[1].w = fmaf(pa.y, hv.w, acc[1].w);
            acc[2].x = fmaf(pa.z, hv.x, acc[2].x); acc[2].y = fmaf(pa.z, hv.y, acc[2].y);
            acc[2].z = fmaf(pa.z, hv.z, acc[2].z); acc[2].w = fmaf(pa.z, hv.w, acc[2].w);
            acc[3].x = fmaf(pa.w, hv.x, acc[3].x); acc[3].y = fmaf(pa.w, hv.y, acc[3].y);
            acc[3].z = fmaf(pa.w, hv.z, acc[3].z); acc[3].w = fmaf(pa.w, hv.w, acc[3].w);
            acc[4].x = fmaf(pb.x, hv.x, acc[4].x); acc[4].y = fmaf(pb.x, hv.y, acc[4].y);
            acc[4].z = fmaf(pb.x, hv.z, acc[4].z); acc[4].w = fmaf(pb.x, hv.w, acc[4].w);
            acc[5].x = fmaf(pb.y, hv.x, acc[5].x); acc[5].y = fmaf(pb.y, hv.y, acc[5].y);
            acc[5].z = fmaf(pb.y, hv.z, acc[5].z); acc[5].w = fmaf(pb.y, hv.w, acc[5].w);
            acc[6].x = fmaf(pb.z, hv.x, acc[6].x); acc[6].y = fmaf(pb.z, hv.y, acc[6].y);
            acc[6].z = fmaf(pb.z, hv.z, acc[6].z); acc[6].w = fmaf(pb.z, hv.w, acc[6].w);
            acc[7].x = fmaf(pb.w, hv.x, acc[7].x); acc[7].y = fmaf(pb.w, hv.y, acc[7].y);
            acc[7].z = fmaf(pb.w, hv.z, acc[7].z); acc[7].w = fmaf(pb.w, hv.w, acc[7].w);
        }
        __syncthreads();   // protect h_sh/p_sh before next staging
    }

    // ---- epilogue: divide by l and store ----
    if (t < 128) l_sh[ha * BM + ia] = l_run;
    __syncthreads();
    float4* o4 = (float4*)out;
#pragma unroll
    for (int r = 0; r < 8; r++) {
        float inv = 1.0f / l_sh[hb * BM + grp * 8 + r];
        float4 v = acc[r];
        v.x *= inv; v.y *= inv; v.z *= inv; v.w *= inv;
        o4[(size_t)(i0 + grp * 8 + r) * 64 + slot] = v;
    }
}

// --------------------------------------------------------------------------
extern "C" void kernel_launch(void* const* d_in, const int* in_sizes, int n_in,
                              void* d_out, int out_size) {
    const float* x     = (const float*)d_in[0];
    const int*   mask  = (const int*)d_in[1];
    const float* W     = (const float*)d_in[2];
    const float* a_src = (const float*)d_in[3];
    const float* a_dst = (const float*)d_in[4];
    float*       out   = (float*)d_out;

    cudaFuncSetAttribute(gat_attn_kernel,
                         cudaFuncAttributeMaxDynamicSharedMemorySize, SM_TOTAL);

    gemm_h_kernel<<<NN / 32, 256>>>(x, W);
    score_vec_kernel<<<(NN * HEADS) / 256, 256>>>(a_src, a_dst);
    gat_attn_kernel<<<NN / BM, 256, SM_TOTAL>>>(mask, out);
}

// round 3
// speedup vs baseline: 3.1585x; 3.1585x over previous
#include <cuda_runtime.h>
#include <math.h>

#define NN      4096
#define IN_DIM  128
#define HEADS   4
#define OUT_DIM 64
#define HD      256   // HEADS*OUT_DIM
#define NB      512   // gather chunk size

// persistent scratch (allocation-free rule: __device__ globals)
__device__ float          g_h[NN * HD];            // 4 MB
__device__ float          g_si[NN * HEADS];
__device__ float          g_sj[NN * HEADS];
__device__ unsigned short g_nbr[(size_t)NN * NN];  // 32 MB padded CSR
__device__ int            g_cnt[NN];

// --------------------------------------------------------------------------
// Kernel 1: h = x @ W    (4096x128) @ (128x256).  16 rows/block, grid 256.
// --------------------------------------------------------------------------
__global__ __launch_bounds__(256) void gemm_h_kernel(const float* __restrict__ x,
                                                     const float* __restrict__ W) {
    __shared__ float xs[16][IN_DIM];
    const int t = threadIdx.x;
    const int row0 = blockIdx.x * 16;

    for (int idx = t; idx < 16 * IN_DIM; idx += 256)
        xs[idx >> 7][idx & 127] = x[row0 * IN_DIM + idx];
    __syncthreads();

    const int slot = t & 63;   // float4 column
    const int grp  = t >> 6;   // 4 row-groups of 4 rows
    float4 acc[4];
#pragma unroll
    for (int r = 0; r < 4; r++) acc[r] = make_float4(0.f, 0.f, 0.f, 0.f);

    const float4* W4 = (const float4*)W;
#pragma unroll 8
    for (int k = 0; k < IN_DIM; k++) {
        float4 wv = W4[k * 64 + slot];
#pragma unroll
        for (int r = 0; r < 4; r++) {
            float xv = xs[grp * 4 + r][k];
            acc[r].x = fmaf(xv, wv.x, acc[r].x);
            acc[r].y = fmaf(xv, wv.y, acc[r].y);
            acc[r].z = fmaf(xv, wv.z, acc[r].z);
            acc[r].w = fmaf(xv, wv.w, acc[r].w);
        }
    }
    float4* H4 = (float4*)g_h;
#pragma unroll
    for (int r = 0; r < 4; r++)
        H4[(size_t)(row0 + grp * 4 + r) * 64 + slot] = acc[r];
}

// --------------------------------------------------------------------------
// Kernel 2: s_i = h . a_src,  s_j = h . a_dst  per (node, head)
// g_sj stored as float4 per node (4 heads together) for the gather kernel.
// --------------------------------------------------------------------------
__global__ __launch_bounds__(256) void score_vec_kernel(const float* __restrict__ a_src,
                                                        const float* __restrict__ a_dst) {
    int t = blockIdx.x * 256 + threadIdx.x;
    if (t >= NN * HEADS) return;
    int n = t >> 2, h = t & 3;
    const float4* hv  = (const float4*)(g_h + (size_t)n * HD + h * OUT_DIM);
    const float4* as4 = (const float4*)a_src;
    const float4* ad4 = (const float4*)a_dst;
    float si = 0.f, sj = 0.f;
#pragma unroll
    for (int q = 0; q < 16; q++) {
        float4 v = hv[q], a = as4[q], b = ad4[q];
        si += v.x * a.x + v.y * a.y + v.z * a.z + v.w * a.w;
        sj += v.x * b.x + v.y * b.y + v.z * b.z + v.w * b.w;
    }
    g_si[n * HEADS + h] = si;
    g_sj[n * HEADS + h] = sj;
}

// --------------------------------------------------------------------------
// Kernel 3: CSR build from int32 adjacency. 1 warp per row, 8 warps/block.
// --------------------------------------------------------------------------
__global__ __launch_bounds__(256) void csr_kernel(const int* __restrict__ mask) {
    const int warp = threadIdx.x >> 5, lane = threadIdx.x & 31;
    const int row  = blockIdx.x * 8 + warp;
    const int4* m4 = (const int4*)mask + (size_t)row * (NN / 4);
    unsigned short* dst = g_nbr + (size_t)row * NN;

    int base = 0;
#pragma unroll 4
    for (int it = 0; it < NN / 128; it++) {          // 32 iters
        int4 v = m4[it * 32 + lane];
        int b0 = (v.x != 0), b1 = (v.y != 0), b2 = (v.z != 0), b3 = (v.w != 0);
        int mycnt = b0 + b1 + b2 + b3;
        // warp inclusive scan
        int off = mycnt;
#pragma unroll
        for (int d = 1; d < 32; d <<= 1) {
            int nn = __shfl_up_sync(0xffffffffu, off, d);
            if (lane >= d) off += nn;
        }
        int total = __shfl_sync(0xffffffffu, off, 31);
        off -= mycnt;                                 // exclusive
        int jb  = (it * 32 + lane) * 4;
        int pos = base + off;
        if (b0) dst[pos++] = (unsigned short)(jb);
        if (b1) dst[pos++] = (unsigned short)(jb + 1);
        if (b2) dst[pos++] = (unsigned short)(jb + 2);
        if (b3) dst[pos++] = (unsigned short)(jb + 3);
        base += total;
    }
    if (lane == 0) g_cnt[row] = base;
}

// --------------------------------------------------------------------------
// Kernel 4: sparse gather attention. 1 block (256 thr) per destination row.
// Online softmax over neighbor chunks of NB; p_j * h[j] accumulation with
// coalesced float4 loads of h rows (L2 resident).
// thread identity: c = t&63 (float4 col over 256 dims, head hc=c>>4),
//                  q = t>>6 (j-subslot, reduced at the end).
// --------------------------------------------------------------------------
__global__ __launch_bounds__(256) void gather_kernel(float* __restrict__ out) {
    __shared__ unsigned short nbr_sh[NB];
    __shared__ float p_sh[HEADS][NB];
    __shared__ float red_sh[HEADS][8];
    __shared__ float bc_sh[2][HEADS];     // [0]=m_new, [1]=chunk sum
    __shared__ float4 acc_sh[4][64];

    const int t    = threadIdx.x;
    const int lane = t & 31;
    const int wid  = t >> 5;
    const int row  = blockIdx.x;
    const int c    = t & 63;
    const int q    = t >> 6;
    const int hc   = c >> 4;

    const int cnt     = g_cnt[row];
    const bool uniform = (cnt == 0);
    const int ecnt    = uniform ? NN : cnt;

    float si[HEADS];
#pragma unroll
    for (int h = 0; h < HEADS; h++) si[h] = g_si[row * HEADS + h];

    float m_run[HEADS], l_run[HEADS];
#pragma unroll
    for (int h = 0; h < HEADS; h++) { m_run[h] = -INFINITY; l_run[h] = 0.f; }

    float4 acc = make_float4(0.f, 0.f, 0.f, 0.f);

    const float4* gh4  = (const float4*)g_h;
    const float4* gsj4 = (const float4*)g_sj;
    const unsigned short* nrow = g_nbr + (size_t)row * NN;

    for (int base = 0; base < ecnt; base += NB) {
        const int cn = min(NB, ecnt - base);

        // ---- stage neighbor indices ----
        for (int jj = t; jj < cn; jj += 256)
            nbr_sh[jj] = uniform ? (unsigned short)(base + jj) : nrow[base + jj];
        __syncthreads();

        // ---- raw scores e -> p_sh, track local max ----
        float lm[HEADS];
#pragma unroll
        for (int h = 0; h < HEADS; h++) lm[h] = -INFINITY;
        for (int jj = t; jj < cn; jj += 256) {
            float4 sj = gsj4[nbr_sh[jj]];
            float e0 = si[0] + sj.x; e0 = fmaxf(e0, 0.2f * e0);
            float e1 = si[1] + sj.y; e1 = fmaxf(e1, 0.2f * e1);
            float e2 = si[2] + sj.z; e2 = fmaxf(e2, 0.2f * e2);
            float e3 = si[3] + sj.w; e3 = fmaxf(e3, 0.2f * e3);
            p_sh[0][jj] = e0; p_sh[1][jj] = e1; p_sh[2][jj] = e2; p_sh[3][jj] = e3;
            lm[0] = fmaxf(lm[0], e0); lm[1] = fmaxf(lm[1], e1);
            lm[2] = fmaxf(lm[2], e2); lm[3] = fmaxf(lm[3], e3);
        }
        // ---- block max reduce per head ----
#pragma unroll
        for (int h = 0; h < HEADS; h++)
#pragma unroll
            for (int d = 16; d; d >>= 1)
                lm[h] = fmaxf(lm[h], __shfl_xor_sync(0xffffffffu, lm[h], d));
        if (lane == 0)
#pragma unroll
            for (int h = 0; h < HEADS; h++) red_sh[h][wid] = lm[h];
        __syncthreads();
        float m_new[HEADS], scale[HEADS];
#pragma unroll
        for (int h = 0; h < HEADS; h++) {
            float cm = red_sh[h][0];
#pragma unroll
            for (int w = 1; w < 8; w++) cm = fmaxf(cm, red_sh[h][w]);
            m_new[h] = fmaxf(m_run[h], cm);
            scale[h] = __expf(m_run[h] - m_new[h]);
        }
        __syncthreads();   // red_sh reuse

        // ---- p = exp(e - m_new), local sums ----
        float ls[HEADS];
#pragma unroll
        for (int h = 0; h < HEADS; h++) ls[h] = 0.f;
        for (int jj = t; jj < cn; jj += 256) {
#pragma unroll
            for (int h = 0; h < HEADS; h++) {
                float p = __expf(p_sh[h][jj] - m_new[h]);
                p_sh[h][jj] = p;
                ls[h] += p;
            }
        }
#pragma unroll
        for (int h = 0; h < HEADS; h++)
#pragma unroll
            for (int d = 16; d; d >>= 1)
                ls[h] += __shfl_xor_sync(0xffffffffu, ls[h], d);
        if (lane == 0)
#pragma unroll
            for (int h = 0; h < HEADS; h++) red_sh[h][wid] = ls[h];
        __syncthreads();
#pragma unroll
        for (int h = 0; h < HEADS; h++) {
            float cs = red_sh[h][0];
#pragma unroll
            for (int w = 1; w < 8; w++) cs += red_sh[h][w];
            l_run[h] = l_run[h] * scale[h] + cs;
            m_run[h] = m_new[h];
        }

        // ---- accumulate p_j * h[j] over this thread's j-subslot ----
        {
            float sc = scale[hc];
            acc.x *= sc; acc.y *= sc; acc.z *= sc; acc.w *= sc;
        }
#pragma unroll 4
        for (int jj = q; jj < cn; jj += 4) {
            int j = nbr_sh[jj];
            float pv = p_sh[hc][jj];
            float4 hv = gh4[(size_t)j * 64 + c];
            acc.x = fmaf(pv, hv.x, acc.x);
            acc.y = fmaf(pv, hv.y, acc.y);
            acc.z = fmaf(pv, hv.z, acc.z);
            acc.w = fmaf(pv, hv.w, acc.w);
        }
        __syncthreads();   // protect nbr_sh / p_sh for next chunk
    }

    // ---- epilogue: reduce q-partials, divide by l, store ----
    acc_sh[q][c] = acc;
    __syncthreads();
    if (t < 64) {
        float4 s = acc_sh[0][t];
        float4 a1 = acc_sh[1][t], a2 = acc_sh[2][t], a3 = acc_sh[3][t];
        s.x += a1.x + a2.x + a3.x;
        s.y += a1.y + a2.y + a3.y;
        s.z += a1.z + a2.z + a3.z;
        s.w += a1.w + a2.w + a3.w;
        float inv = 1.0f / l_run[t >> 4];
        s.x *= inv; s.y *= inv; s.z *= inv; s.w *= inv;
        ((float4*)out)[(size_t)row * 64 + t] = s;
    }
}

// --------------------------------------------------------------------------
extern "C" void kernel_launch(void* const* d_in, const int* in_sizes, int n_in,
                              void* d_out, int out_size) {
    const float* x     = (const float*)d_in[0];
    const int*   mask  = (const int*)d_in[1];
    const float* W     = (const float*)d_in[2];
    const float* a_src = (const float*)d_in[3];
    const float* a_dst = (const float*)d_in[4];
    float*       out   = (float*)d_out;

    gemm_h_kernel<<<NN / 16, 256>>>(x, W);
    score_vec_kernel<<<(NN * HEADS) / 256, 256>>>(a_src, a_dst);
    csr_kernel<<<NN / 8, 256>>>(mask);
    gather_kernel<<<NN, 256>>>(out);
}

// round 4
// speedup vs baseline: 3.5081x; 1.1107x over previous
#include <cuda_runtime.h>
#include <math.h>

#define NN      4096
#define IN_DIM  128
#define HEADS   4
#define OUT_DIM 64
#define HD      256   // HEADS*OUT_DIM
#define NB      512   // gather chunk size

// persistent scratch (allocation-free rule: __device__ globals)
__device__ float          g_h[NN * HD];            // 4 MB
__device__ float          g_si[NN * HEADS];
__device__ float          g_sj[NN * HEADS];
__device__ float          g_mx[HEADS];             // global max of sj per head
__device__ unsigned short g_nbr[(size_t)NN * NN];  // 32 MB padded CSR
__device__ int            g_cnt[NN];

// --------------------------------------------------------------------------
// Kernel 1: h = x @ W    (4096x128) @ (128x256).  16 rows/block, grid 256.
// --------------------------------------------------------------------------
__global__ __launch_bounds__(256) void gemm_h_kernel(const float* __restrict__ x,
                                                     const float* __restrict__ W) {
    __shared__ float xs[16][IN_DIM];
    const int t = threadIdx.x;
    const int row0 = blockIdx.x * 16;

    for (int idx = t; idx < 16 * IN_DIM; idx += 256)
        xs[idx >> 7][idx & 127] = x[row0 * IN_DIM + idx];
    __syncthreads();

    const int slot = t & 63;   // float4 column
    const int grp  = t >> 6;   // 4 row-groups of 4 rows
    float4 acc[4];
#pragma unroll
    for (int r = 0; r < 4; r++) acc[r] = make_float4(0.f, 0.f, 0.f, 0.f);

    const float4* W4 = (const float4*)W;
#pragma unroll 8
    for (int k = 0; k < IN_DIM; k++) {
        float4 wv = W4[k * 64 + slot];
#pragma unroll
        for (int r = 0; r < 4; r++) {
            float xv = xs[grp * 4 + r][k];
            acc[r].x = fmaf(xv, wv.x, acc[r].x);
            acc[r].y = fmaf(xv, wv.y, acc[r].y);
            acc[r].z = fmaf(xv, wv.z, acc[r].z);
            acc[r].w = fmaf(xv, wv.w, acc[r].w);
        }
    }
    float4* H4 = (float4*)g_h;
#pragma unroll
    for (int r = 0; r < 4; r++)
        H4[(size_t)(row0 + grp * 4 + r) * 64 + slot] = acc[r];
}

// --------------------------------------------------------------------------
// Kernel 2: s_i = h . a_src,  s_j = h . a_dst  per (node, head)
// --------------------------------------------------------------------------
__global__ __launch_bounds__(256) void score_vec_kernel(const float* __restrict__ a_src,
                                                        const float* __restrict__ a_dst) {
    int t = blockIdx.x * 256 + threadIdx.x;
    if (t >= NN * HEADS) return;
    int n = t >> 2, h = t & 3;
    const float4* hv  = (const float4*)(g_h + (size_t)n * HD + h * OUT_DIM);
    const float4* as4 = (const float4*)a_src;
    const float4* ad4 = (const float4*)a_dst;
    float si = 0.f, sj = 0.f;
#pragma unroll
    for (int q = 0; q < 16; q++) {
        float4 v = hv[q], a = as4[q], b = ad4[q];
        si += v.x * a.x + v.y * a.y + v.z * a.z + v.w * a.w;
        sj += v.x * b.x + v.y * b.y + v.z * b.z + v.w * b.w;
    }
    g_si[n * HEADS + h] = si;
    g_sj[n * HEADS + h] = sj;
}

// --------------------------------------------------------------------------
// Kernel 2b: g_mx[h] = max_n g_sj[n][h]. One block.
// --------------------------------------------------------------------------
__global__ __launch_bounds__(256) void max_sj_kernel() {
    __shared__ float red[HEADS][8];
    const int t = threadIdx.x, lane = t & 31, wid = t >> 5;
    float mx[HEADS];
#pragma unroll
    for (int h = 0; h < HEADS; h++) mx[h] = -INFINITY;
    const float4* s4 = (const float4*)g_sj;
    for (int i = t; i < NN; i += 256) {
        float4 v = s4[i];
        mx[0] = fmaxf(mx[0], v.x); mx[1] = fmaxf(mx[1], v.y);
        mx[2] = fmaxf(mx[2], v.z); mx[3] = fmaxf(mx[3], v.w);
    }
#pragma unroll
    for (int h = 0; h < HEADS; h++)
#pragma unroll
        for (int d = 16; d; d >>= 1)
            mx[h] = fmaxf(mx[h], __shfl_xor_sync(0xffffffffu, mx[h], d));
    if (lane == 0)
#pragma unroll
        for (int h = 0; h < HEADS; h++) red[h][wid] = mx[h];
    __syncthreads();
    if (t < HEADS) {
        float m = red[t][0];
#pragma unroll
        for (int w = 1; w < 8; w++) m = fmaxf(m, red[t][w]);
        g_mx[t] = m;
    }
}

// --------------------------------------------------------------------------
// Kernel 3: CSR build from int32 adjacency. 1 warp per row, 8 warps/block.
// --------------------------------------------------------------------------
__global__ __launch_bounds__(256) void csr_kernel(const int* __restrict__ mask) {
    const int warp = threadIdx.x >> 5, lane = threadIdx.x & 31;
    const int row  = blockIdx.x * 8 + warp;
    const int4* m4 = (const int4*)mask + (size_t)row * (NN / 4);
    unsigned short* dst = g_nbr + (size_t)row * NN;

    int base = 0;
#pragma unroll 4
    for (int it = 0; it < NN / 128; it++) {          // 32 iters
        int4 v = m4[it * 32 + lane];
        int b0 = (v.x != 0), b1 = (v.y != 0), b2 = (v.z != 0), b3 = (v.w != 0);
        int mycnt = b0 + b1 + b2 + b3;
        int off = mycnt;
#pragma unroll
        for (int d = 1; d < 32; d <<= 1) {
            int nn = __shfl_up_sync(0xffffffffu, off, d);
            if (lane >= d) off += nn;
        }
        int total = __shfl_sync(0xffffffffu, off, 31);
        off -= mycnt;                                 // exclusive
        int jb  = (it * 32 + lane) * 4;
        int pos = base + off;
        if (b0) dst[pos++] = (unsigned short)(jb);
        if (b1) dst[pos++] = (unsigned short)(jb + 1);
        if (b2) dst[pos++] = (unsigned short)(jb + 2);
        if (b3) dst[pos++] = (unsigned short)(jb + 3);
        base += total;
    }
    if (lane == 0) g_cnt[row] = base;
}

// --------------------------------------------------------------------------
// Kernel 4: sparse gather attention, SINGLE-PASS softmax.
// m[h] = lrelu(si[h] + g_mx[h]) >= all row scores (lrelu monotone), so
// p = exp(e - m) is stable and sums/outputs match softmax exactly after /sum.
// --------------------------------------------------------------------------
__global__ __launch_bounds__(256) void gather_kernel(float* __restrict__ out) {
    __shared__ unsigned short nbr_sh[NB];
    __shared__ float p_sh[HEADS][NB];
    __shared__ float red_sh[HEADS][8];
    __shared__ float4 acc_sh[4][64];

    const int t    = threadIdx.x;
    const int lane = t & 31;
    const int wid  = t >> 5;
    const int row  = blockIdx.x;
    const int c    = t & 63;      // float4 column over 256 dims
    const int q    = t >> 6;      // j-subslot
    const int hc   = c >> 4;      // head owned in acc pass

    const int cnt      = g_cnt[row];
    const bool uniform = (cnt == 0);
    const int ecnt     = uniform ? NN : cnt;

    float m[HEADS], sum[HEADS];
#pragma unroll
    for (int h = 0; h < HEADS; h++) {
        float v = g_si[row * HEADS + h] + g_mx[h];
        m[h] = fmaxf(v, 0.2f * v);        // lrelu
        sum[h] = 0.f;
    }
    float si[HEADS];
#pragma unroll
    for (int h = 0; h < HEADS; h++) si[h] = g_si[row * HEADS + h];

    float4 acc = make_float4(0.f, 0.f, 0.f, 0.f);

    const float4* gh4  = (const float4*)g_h;
    const float4* gsj4 = (const float4*)g_sj;
    const unsigned short* nrow = g_nbr + (size_t)row * NN;

    for (int base = 0; base < ecnt; base += NB) {
        const int cn = min(NB, ecnt - base);

        for (int jj = t; jj < cn; jj += 256)
            nbr_sh[jj] = uniform ? (unsigned short)(base + jj) : nrow[base + jj];
        __syncthreads();

        // ---- p-pass: e -> p, accumulate sums in registers ----
        for (int jj = t; jj < cn; jj += 256) {
            float4 sj = gsj4[nbr_sh[jj]];
            float e0 = si[0] + sj.x; e0 = fmaxf(e0, 0.2f * e0);
            float e1 = si[1] + sj.y; e1 = fmaxf(e1, 0.2f * e1);
            float e2 = si[2] + sj.z; e2 = fmaxf(e2, 0.2f * e2);
            float e3 = si[3] + sj.w; e3 = fmaxf(e3, 0.2f * e3);
            float p0 = __expf(e0 - m[0]);
            float p1 = __expf(e1 - m[1]);
            float p2 = __expf(e2 - m[2]);
            float p3 = __expf(e3 - m[3]);
            p_sh[0][jj] = p0; p_sh[1][jj] = p1;
            p_sh[2][jj] = p2; p_sh[3][jj] = p3;
            sum[0] += p0; sum[1] += p1; sum[2] += p2; sum[3] += p3;
        }
        __syncthreads();

        // ---- acc-pass: acc += p_j * h[j] ----
#pragma unroll 8
        for (int jj = q; jj < cn; jj += 4) {
            int j = nbr_sh[jj];
            float pv = p_sh[hc][jj];
            float4 hv = gh4[(size_t)j * 64 + c];
            acc.x = fmaf(pv, hv.x, acc.x);
            acc.y = fmaf(pv, hv.y, acc.y);
            acc.z = fmaf(pv, hv.z, acc.z);
            acc.w = fmaf(pv, hv.w, acc.w);
        }
        __syncthreads();
    }

    // ---- one-time reductions ----
#pragma unroll
    for (int h = 0; h < HEADS; h++)
#pragma unroll
        for (int d = 16; d; d >>= 1)
            sum[h] += __shfl_xor_sync(0xffffffffu, sum[h], d);
    if (lane == 0)
#pragma unroll
        for (int h = 0; h < HEADS; h++) red_sh[h][wid] = sum[h];
    acc_sh[q][c] = acc;
    __syncthreads();

    if (t < 64) {
        float4 s  = acc_sh[0][t];
        float4 a1 = acc_sh[1][t], a2 = acc_sh[2][t], a3 = acc_sh[3][t];
        s.x += a1.x + a2.x + a3.x;
        s.y += a1.y + a2.y + a3.y;
        s.z += a1.z + a2.z + a3.z;
        s.w += a1.w + a2.w + a3.w;
        int hh = t >> 4;
        float tot = 0.f;
#pragma unroll
        for (int w = 0; w < 8; w++) tot += red_sh[hh][w];
        float inv = 1.0f / tot;
        s.x *= inv; s.y *= inv; s.z *= inv; s.w *= inv;
        ((float4*)out)[(size_t)row * 64 + t] = s;
    }
}

// --------------------------------------------------------------------------
extern "C" void kernel_launch(void* const* d_in, const int* in_sizes, int n_in,
                              void* d_out, int out_size) {
    const float* x     = (const float*)d_in[0];
    const int*   mask  = (const int*)d_in[1];
    const float* W     = (const float*)d_in[2];
    const float* a_src = (const float*)d_in[3];
    const float* a_dst = (const float*)d_in[4];
    float*       out   = (float*)d_out;

    gemm_h_kernel<<<NN / 16, 256>>>(x, W);
    score_vec_kernel<<<(NN * HEADS) / 256, 256>>>(a_src, a_dst);
    max_sj_kernel<<<1, 256>>>();
    csr_kernel<<<NN / 8, 256>>>(mask);
    gather_kernel<<<NN, 256>>>(out);
}